// round 14
// baseline (speedup 1.0000x reference)
#include <cuda_runtime.h>
#include <cfloat>
#include <math.h>

// Problem constants
#define NN 16384
#define MM 32768
#define KK 8
#define CC 256
#define PS 2560                // padded slots per chunk (pop ~2048 +- 45)
#define NCHUNK 16              // chunks = (x,y) cell columns of a 4x4x4 grid

// Scratch (device globals; no allocations allowed)
__device__ int g_chist[64];                 // cond cell histogram
__device__ int g_cstart[65];                // exclusive scan of cell counts
__device__ int g_ccur[64];                  // scatter cursors
__device__ int g_cnsteps[NCHUNK];           // ceil(pop/128) per chunk
// +256 floats slack so the unconditional prefetch of step+1 never goes OOB
__device__ __align__(16) float g_px[NCHUNK * PS + 256];
__device__ __align__(16) float g_py[NCHUNK * PS + 256];
__device__ __align__(16) float g_pz[NCHUNK * PS + 256];
__device__ __align__(16) int   g_pidx[NCHUNK * PS + 256];
__device__ float g_favg[NN * CC];      // weighted-average features
__device__ float g_h1[NN * CC];        // MLP intermediate 1
__device__ float g_h2[NN * CC];        // MLP intermediate 2
__device__ float g_tf[CC];             // timestep feature vector

// ---------------------------------------------------------------------------
// Prep kernels (all tiny)
// ---------------------------------------------------------------------------
__global__ void k_zero() {
    if (threadIdx.x < 64) g_chist[threadIdx.x] = 0;
}

__global__ void k_hist(const int* __restrict__ cond_c) {
    __shared__ int h[64];
    int tid = threadIdx.x;
    if (tid < 64) h[tid] = 0;
    __syncthreads();
    int i = blockIdx.x * 256 + tid;
    int4 cc = ((const int4*)cond_c)[i];
    int cell = ((cc.y >> 8) << 4) | ((cc.z >> 8) << 2) | (cc.w >> 8);
    atomicAdd(&h[cell], 1);
    __syncthreads();
    if (tid < 64 && h[tid]) atomicAdd(&g_chist[tid], h[tid]);
}

__global__ void k_scan64() {   // serial scan by t0 (64 elements, trivial)
    if (threadIdx.x == 0) {
        int acc = 0;
        for (int j = 0; j < 64; ++j) {
            int v = g_chist[j];
            g_cstart[j] = acc;
            g_ccur[j] = acc;
            acc += v;
        }
        g_cstart[64] = acc;
        for (int c = 0; c < NCHUNK; ++c) {
            int pop = g_cstart[4 * c + 4] - g_cstart[4 * c];
            g_cnsteps[c] = (pop + 127) >> 7;
        }
    }
}

__global__ void k_fill() {     // sentinel-fill padded arrays (+slack)
    int i = blockIdx.x * 256 + threadIdx.x;
    if (i < NCHUNK * PS + 256) {
        g_px[i] = 1e18f;
        g_py[i] = 1e18f;
        g_pz[i] = 1e18f;
        g_pidx[i] = 0x7ffffffe;
    }
}

__global__ void k_scatter(const int* __restrict__ cond_c) {
    int i = blockIdx.x * 256 + threadIdx.x;
    int4 cc = ((const int4*)cond_c)[i];
    int cell = ((cc.y >> 8) << 4) | ((cc.z >> 8) << 2) | (cc.w >> 8);
    int pos = atomicAdd(&g_ccur[cell], 1);          // global rank within cell run
    int chunk = cell >> 2;
    int pidx = chunk * PS + (pos - g_cstart[(chunk << 2)]);
    // exact reference transform, negated (dx = add(nx, negcx))
    g_px[pidx] = -__fmul_rn(__fadd_rn((float)cc.y, 0.5f), 0.01f);
    g_py[pidx] = -__fmul_rn(__fadd_rn((float)cc.z, 0.5f), 0.01f);
    g_pz[pidx] = -__fmul_rn(__fadd_rn((float)cc.w, 0.5f), 0.01f);
    g_pidx[pidx] = i;
}

// ---------------------------------------------------------------------------
// Kernel 1: timestep embedding -> 2-layer MLP -> g_tf[256]
// ---------------------------------------------------------------------------
__global__ void k_tfeats(const float* __restrict__ t,
                         const float* __restrict__ Wt1, const float* __restrict__ bt1,
                         const float* __restrict__ Wt2, const float* __restrict__ bt2) {
    __shared__ float emb[96];
    __shared__ float h1[96];
    int tid = threadIdx.x;
    float tv = t[0];
    if (tid < 48) {
        const double c64 = -9.210340371976184 / 47.0;
        float cf = (float)c64;
        float arg = __fmul_rn((float)tid, cf);
        float f = (float)exp((double)arg);
        float e = __fmul_rn(tv, f);
        emb[tid]      = (float)sin((double)e);
        emb[tid + 48] = (float)cos((double)e);
    }
    __syncthreads();
    if (tid < 96) {
        float acc = 0.0f;
        #pragma unroll 8
        for (int j = 0; j < 96; ++j) acc += emb[j] * Wt1[tid * 96 + j];
        acc += bt1[tid];
        h1[tid] = (acc >= 0.0f) ? acc : 0.1f * acc;
    }
    __syncthreads();
    if (tid < 256) {
        float acc = 0.0f;
        #pragma unroll 8
        for (int j = 0; j < 96; ++j) acc += h1[j] * Wt2[tid * 96 + j];
        acc += bt2[tid];
        g_tf[tid] = acc;
    }
}

// ---------------------------------------------------------------------------
// Packed f32x2 helpers (two independent IEEE-RN fp32 lanes -> bit-exact)
// ---------------------------------------------------------------------------
__device__ __forceinline__ unsigned long long pack2(float x) {
    unsigned long long r;
    asm("mov.b64 %0, {%1, %1};" : "=l"(r) : "f"(x));
    return r;
}

__device__ __forceinline__ void ffma2(unsigned long long& acc,
                                      unsigned long long a, unsigned long long b) {
    asm("fma.rn.f32x2 %0, %1, %2, %0;" : "+l"(acc) : "l"(a), "l"(b));
}

__device__ __forceinline__ void unpack2(unsigned long long v, float& lo, float& hi) {
    asm("mov.b64 {%0, %1}, %2;" : "=f"(lo), "=f"(hi) : "l"(v));
}

// d_lane = fma(dz,dz, fma(dy,dy, dx*dx)) with dx = nx + (-cx)  (XLA scheme)
__device__ __forceinline__ void dist2x2(unsigned long long nx, unsigned long long ny,
                                        unsigned long long nz,
                                        unsigned long long cx, unsigned long long cy,
                                        unsigned long long cz,
                                        float& d0, float& d1) {
    asm("{\n\t"
        ".reg .b64 dx, dy, dz, t;\n\t"
        "add.rn.f32x2 dx, %2, %5;\n\t"
        "add.rn.f32x2 dy, %3, %6;\n\t"
        "add.rn.f32x2 dz, %4, %7;\n\t"
        "mul.rn.f32x2 t, dx, dx;\n\t"
        "fma.rn.f32x2 t, dy, dy, t;\n\t"
        "fma.rn.f32x2 t, dz, dz, t;\n\t"
        "mov.b64 {%0, %1}, t;\n\t"
        "}"
        : "=f"(d0), "=f"(d1)
        : "l"(nx), "l"(ny), "l"(nz), "l"(cx), "l"(cy), "l"(cz));
}

// Lexicographic (d, idx) insert: order-independent, equals top_k's selection
// and tie rule (ascending d, ties by lower original index).
__device__ __forceinline__ void insertlex(float d, int idx, float* bd, int* bi) {
    if (d < bd[KK - 1] || (d == bd[KK - 1] && idx < bi[KK - 1])) {
        bd[KK - 1] = d;
        bi[KK - 1] = idx;
        #pragma unroll
        for (int q = KK - 1; q > 0; --q) {
            if (bd[q] < bd[q - 1] || (bd[q] == bd[q - 1] && bi[q] < bi[q - 1])) {
                float td = bd[q]; bd[q] = bd[q - 1]; bd[q - 1] = td;
                int   ti = bi[q]; bi[q] = bi[q - 1]; bi[q - 1] = ti;
            }
        }
    }
}

union F4U {
    float4 v;
    unsigned long long u[2];
};

// Analytic chunk AABB lower-bound distance^2 (chunk = (x,y) cell column).
__device__ __forceinline__ float chunk_lb(int c, float nx, float ny, float nz) {
    float xlo = (float)(c >> 2) * 2.56f + 0.005f;
    float ylo = (float)(c & 3)  * 2.56f + 0.005f;
    float dx = fmaxf(fmaxf(xlo - nx, nx - (xlo + 2.55f)), 0.f);
    float dy = fmaxf(fmaxf(ylo - ny, ny - (ylo + 2.55f)), 0.f);
    float dz = fmaxf(fmaxf(0.005f - nz, nz - 10.235f), 0.f);
    return dx * dx + dy * dy + dz * dz;
}

// Warp-cooperative scan of one padded chunk from L2, software-pipelined:
// step i+1's loads issue before step i's compute consumes step i's data.
__device__ __forceinline__ void process_chunk(
    int c, int lane, int nsteps,
    unsigned long long px, unsigned long long py, unsigned long long pz,
    float* bd, int* bi, float& thr)
{
    const unsigned FULL = 0xffffffffu;
    const float4* gx = (const float4*)(g_px + c * PS);
    const float4* gy = (const float4*)(g_py + c * PS);
    const float4* gz = (const float4*)(g_pz + c * PS);

    F4U X, Y, Z;
    X.v = gx[lane];
    Y.v = gy[lane];
    Z.v = gz[lane];

    #pragma unroll 1
    for (int step = 0; step < nsteps; ++step) {
        // prefetch next step (always in-bounds thanks to +256 slack)
        F4U Xn, Yn, Zn;
        int jn = (step + 1) * 32 + lane;
        Xn.v = gx[jn];
        Yn.v = gy[jn];
        Zn.v = gz[jn];

        float d0, d1, d2, d3;
        dist2x2(px, py, pz, X.u[0], Y.u[0], Z.u[0], d0, d1);
        dist2x2(px, py, pz, X.u[1], Y.u[1], Z.u[1], d2, d3);
        float mn = fminf(fminf(d0, d1), fminf(d2, d3));
        unsigned mask = __ballot_sync(FULL, mn <= thr);
        while (mask) {
            int b = __ffs(mask) - 1; mask &= mask - 1;
            float bm = __shfl_sync(FULL, mn, b);
            if (bm > thr) continue;            // thr tightened since ballot
            float e0 = __shfl_sync(FULL, d0, b);
            float e1 = __shfl_sync(FULL, d1, b);
            float e2 = __shfl_sync(FULL, d2, b);
            float e3 = __shfl_sync(FULL, d3, b);
            int4 iq = *(const int4*)&g_pidx[c * PS + step * 128 + b * 4];
            insertlex(e0, iq.x, bd, bi);
            insertlex(e1, iq.y, bd, bi);
            insertlex(e2, iq.z, bd, bi);
            insertlex(e3, iq.w, bd, bi);
            thr = bd[KK - 1];
        }

        X = Xn; Y = Yn; Z = Zn;
    }
}

// ---------------------------------------------------------------------------
// Kernel 2: branch-and-bound exact KNN + weights + feature gather, fused.
// 1 node per warp, independent warps, zero smem/syncs. Warm-up on the
// analytically-nearest chunk, then prune the rest by AABB lower bound with
// conservative slop. Lex (d, idx) selection = exact reference top_k.
// ---------------------------------------------------------------------------
__global__ void __launch_bounds__(256) k_knn(const int* __restrict__ node_c,
                                             const float* __restrict__ cond_feats) {
    const int warp = threadIdx.x >> 5;
    const int lane = threadIdx.x & 31;
    const int n = blockIdx.x * 8 + warp;

    int4 nc = ((const int4*)node_c)[n];
    float nx = __fmul_rn(__fadd_rn((float)nc.y, 8.0f), 0.05f);
    float ny = __fmul_rn(__fadd_rn((float)nc.z, 8.0f), 0.05f);
    float nz = __fmul_rn(__fadd_rn((float)nc.w, 8.0f), 0.05f);
    unsigned long long px = pack2(nx), py = pack2(ny), pz = pack2(nz);

    float bd[KK];
    int   bi[KK];
    #pragma unroll
    for (int s = 0; s < KK; ++s) { bd[s] = FLT_MAX; bi[s] = 0x7fffffff; }
    float thr = FLT_MAX;

    // warm-up: analytically nearest chunk
    int cbest = 0;
    {
        float best = FLT_MAX;
        #pragma unroll
        for (int c = 0; c < NCHUNK; ++c) {
            float lb = chunk_lb(c, nx, ny, nz);
            if (lb < best) { best = lb; cbest = c; }
        }
    }
    process_chunk(cbest, lane, g_cnsteps[cbest], px, py, pz, bd, bi, thr);

    // prune remaining chunks
    #pragma unroll 1
    for (int c = 0; c < NCHUNK; ++c) {
        if (c == cbest) continue;
        float lb = chunk_lb(c, nx, ny, nz);
        if (__fmaf_rn(lb, 0.999f, -0.01f) <= thr)
            process_chunk(c, lane, g_cnsteps[c], px, py, pz, bd, bi, thr);
    }

    // fused epilogue: weights + weighted feature gather (state replicated;
    // bd ascending lex = reference summation order)
    float w[KK];
    float wsum = 0.0f;
    #pragma unroll
    for (int k = 0; k < KK; ++k) {
        float dist = fmaxf(sqrtf(bd[k]), 1e-6f);
        w[k] = 1.0f / dist;
        wsum += w[k];
    }
    #pragma unroll
    for (int k = 0; k < KK; ++k) w[k] = w[k] / wsum;

    const float* rp[KK];
    #pragma unroll
    for (int k = 0; k < KK; ++k) rp[k] = cond_feats + (size_t)bi[k] * CC;

    float* outp = g_favg + (size_t)n * CC;
    #pragma unroll
    for (int j = 0; j < 8; ++j) {
        int c = lane + j * 32;
        float acc = 0.0f;
        #pragma unroll
        for (int k = 0; k < KK; ++k) acc = fmaf(w[k], rp[k][c], acc);
        outp[c] = acc;
    }
}

// ---------------------------------------------------------------------------
// Kernel 4: packed-f32x2 SGEMM  Y[16384,256] = X @ W^T (+bias, act, tf)
// (proven 60.5us variant, unchanged)
// ---------------------------------------------------------------------------
#define SP 132   // smem pitch (floats)
template<int ACT, int ADDTF>
__global__ void __launch_bounds__(256, 2) k_gemm(const float* __restrict__ X,
                                                 const float* __restrict__ W,
                                                 const float* __restrict__ bias,
                                                 float* __restrict__ Y) {
    __shared__ float As[2][8][SP];
    __shared__ float Bs[2][8][SP];

    const int t   = threadIdx.x;
    const int tx  = t & 15;
    const int ty  = t >> 4;
    const int row0 = blockIdx.x * 128;
    const int col0 = blockIdx.y * 128;

    const int lrow = t >> 1;
    const int lk4  = (t & 1) * 4;
    const float* Ag = X + (size_t)(row0 + lrow) * CC + lk4;
    const float* Bg = W + (size_t)(col0 + lrow) * CC + lk4;

    float4 afrag = *(const float4*)Ag;
    float4 bfrag = *(const float4*)Bg;

    As[0][lk4 + 0][lrow] = afrag.x;
    As[0][lk4 + 1][lrow] = afrag.y;
    As[0][lk4 + 2][lrow] = afrag.z;
    As[0][lk4 + 3][lrow] = afrag.w;
    Bs[0][lk4 + 0][lrow] = bfrag.x;
    Bs[0][lk4 + 1][lrow] = bfrag.y;
    Bs[0][lk4 + 2][lrow] = bfrag.z;
    Bs[0][lk4 + 3][lrow] = bfrag.w;
    __syncthreads();

    unsigned long long acc2[4][8];
    #pragma unroll
    for (int i = 0; i < 4; ++i)
        #pragma unroll
        for (int j = 0; j < 8; ++j) acc2[i][j] = 0ull;

    #pragma unroll 1
    for (int kt = 0; kt < 32; ++kt) {
        int buf = kt & 1;
        if (kt < 31) {
            afrag = *(const float4*)(Ag + (kt + 1) * 8);
            bfrag = *(const float4*)(Bg + (kt + 1) * 8);
        }

        #pragma unroll
        for (int kk = 0; kk < 8; ++kk) {
            F4U a0, a1, b0, b1;
            a0.v = *(const float4*)&As[buf][kk][ty * 8];
            a1.v = *(const float4*)&As[buf][kk][ty * 8 + 4];
            b0.v = *(const float4*)&Bs[buf][kk][tx * 8];
            b1.v = *(const float4*)&Bs[buf][kk][tx * 8 + 4];

            unsigned long long ap[4] = {a0.u[0], a0.u[1], a1.u[0], a1.u[1]};
            unsigned long long bp[8];
            bp[0] = pack2(b0.v.x); bp[1] = pack2(b0.v.y);
            bp[2] = pack2(b0.v.z); bp[3] = pack2(b0.v.w);
            bp[4] = pack2(b1.v.x); bp[5] = pack2(b1.v.y);
            bp[6] = pack2(b1.v.z); bp[7] = pack2(b1.v.w);

            #pragma unroll
            for (int i = 0; i < 4; ++i)
                #pragma unroll
                for (int j = 0; j < 8; ++j)
                    ffma2(acc2[i][j], ap[i], bp[j]);
        }

        if (kt < 31) {
            int nb = buf ^ 1;
            As[nb][lk4 + 0][lrow] = afrag.x;
            As[nb][lk4 + 1][lrow] = afrag.y;
            As[nb][lk4 + 2][lrow] = afrag.z;
            As[nb][lk4 + 3][lrow] = afrag.w;
            Bs[nb][lk4 + 0][lrow] = bfrag.x;
            Bs[nb][lk4 + 1][lrow] = bfrag.y;
            Bs[nb][lk4 + 2][lrow] = bfrag.z;
            Bs[nb][lk4 + 3][lrow] = bfrag.w;
            __syncthreads();
        }
    }

    float bb[8], tf[8];
    #pragma unroll
    for (int j = 0; j < 8; ++j) {
        int c = col0 + tx * 8 + j;
        bb[j] = bias[c];
        if (ADDTF) tf[j] = g_tf[c];
    }

    #pragma unroll
    for (int i2 = 0; i2 < 4; ++i2) {
        float oL[8], oH[8];
        #pragma unroll
        for (int j = 0; j < 8; ++j) {
            float lo, hi;
            unpack2(acc2[i2][j], lo, hi);
            float vL = lo + bb[j];
            float vH = hi + bb[j];
            if (ACT) {
                vL = (vL >= 0.0f) ? vL : 0.1f * vL;
                vH = (vH >= 0.0f) ? vH : 0.1f * vH;
            }
            if (ADDTF) { vL += tf[j]; vH += tf[j]; }
            oL[j] = vL; oH[j] = vH;
        }
        int rL = row0 + ty * 8 + 2 * i2;
        float4* ypL = (float4*)(Y + (size_t)rL * CC + col0 + tx * 8);
        ypL[0] = make_float4(oL[0], oL[1], oL[2], oL[3]);
        ypL[1] = make_float4(oL[4], oL[5], oL[6], oL[7]);
        float4* ypH = (float4*)(Y + (size_t)(rL + 1) * CC + col0 + tx * 8);
        ypH[0] = make_float4(oH[0], oH[1], oH[2], oH[3]);
        ypH[1] = make_float4(oH[4], oH[5], oH[6], oH[7]);
    }
}

// ---------------------------------------------------------------------------
extern "C" void kernel_launch(void* const* d_in, const int* in_sizes, int n_in,
                              void* d_out, int out_size) {
    const int*   node_c     = (const int*)d_in[0];
    const int*   cond_c     = (const int*)d_in[1];
    const float* cond_feats = (const float*)d_in[2];
    const float* t          = (const float*)d_in[3];
    const float* W_proj     = (const float*)d_in[4];
    const float* b_proj     = (const float*)d_in[5];
    const float* W_l1       = (const float*)d_in[6];
    const float* b_l1       = (const float*)d_in[7];
    const float* W_l2       = (const float*)d_in[8];
    const float* b_l2       = (const float*)d_in[9];
    const float* W_t1       = (const float*)d_in[10];
    const float* b_t1       = (const float*)d_in[11];
    const float* W_t2       = (const float*)d_in[12];
    const float* b_t2       = (const float*)d_in[13];
    float* out = (float*)d_out;

    float* h1; cudaGetSymbolAddress((void**)&h1, g_h1);
    float* h2; cudaGetSymbolAddress((void**)&h2, g_h2);
    float* fa; cudaGetSymbolAddress((void**)&fa, g_favg);

    // prep: cell histogram -> scan -> sentinel fill -> padded chunked scatter
    k_zero<<<1, 64>>>();
    k_hist<<<MM / 256, 256>>>(cond_c);
    k_scan64<<<1, 64>>>();
    k_fill<<<(NCHUNK * PS + 256 + 255) / 256, 256>>>();
    k_scatter<<<MM / 256, 256>>>(cond_c);

    k_tfeats<<<1, 256>>>(t, W_t1, b_t1, W_t2, b_t2);

    k_knn<<<NN / 8, 256>>>(node_c, cond_feats);   // 2048 blocks, 1 node/warp

    dim3 gg(NN / 128, CC / 128);
    k_gemm<0, 0><<<gg, 256>>>(fa, W_proj, b_proj, h1);
    k_gemm<1, 0><<<gg, 256>>>(h1, W_l1, b_l1, h2);
    k_gemm<0, 1><<<gg, 256>>>(h2, W_l2, b_l2, out);

    (void)in_sizes; (void)n_in; (void)out_size;
}

// round 15
// speedup vs baseline: 1.3363x; 1.3363x over previous
#include <cuda_runtime.h>
#include <cfloat>
#include <math.h>

// Problem constants
#define NN 16384
#define MM 32768
#define KK 8
#define CC 256
#define TILE 2048             // cond candidates per shared tile
#define NTILES (MM / TILE)    // 16

// Scratch (device globals; no allocations allowed)
__device__ __align__(16) float g_cx[MM];   // negated transformed cond x
__device__ __align__(16) float g_cy[MM];
__device__ __align__(16) float g_cz[MM];
__device__ float g_favg[NN * CC];      // weighted-average features
__device__ float g_h1[NN * CC];        // MLP intermediate 1
__device__ float g_h2[NN * CC];        // MLP intermediate 2
__device__ float g_tf[CC];             // timestep feature vector

// ---------------------------------------------------------------------------
// Kernel 0: pre-transform cond coords (negated, SoA)
// ---------------------------------------------------------------------------
__global__ void k_prep(const int* __restrict__ cond_c) {
    int i = blockIdx.x * 256 + threadIdx.x;
    int4 cc = ((const int4*)cond_c)[i];
    g_cx[i] = -__fmul_rn(__fadd_rn((float)cc.y, 0.5f), 0.01f);
    g_cy[i] = -__fmul_rn(__fadd_rn((float)cc.z, 0.5f), 0.01f);
    g_cz[i] = -__fmul_rn(__fadd_rn((float)cc.w, 0.5f), 0.01f);
}

// ---------------------------------------------------------------------------
// Kernel 1: timestep embedding -> 2-layer MLP -> g_tf[256]
// ---------------------------------------------------------------------------
__global__ void k_tfeats(const float* __restrict__ t,
                         const float* __restrict__ Wt1, const float* __restrict__ bt1,
                         const float* __restrict__ Wt2, const float* __restrict__ bt2) {
    __shared__ float emb[96];
    __shared__ float h1[96];
    int tid = threadIdx.x;
    float tv = t[0];
    if (tid < 48) {
        const double c64 = -9.210340371976184 / 47.0;
        float cf = (float)c64;
        float arg = __fmul_rn((float)tid, cf);
        float f = (float)exp((double)arg);
        float e = __fmul_rn(tv, f);
        emb[tid]      = (float)sin((double)e);
        emb[tid + 48] = (float)cos((double)e);
    }
    __syncthreads();
    if (tid < 96) {
        float acc = 0.0f;
        #pragma unroll 8
        for (int j = 0; j < 96; ++j) acc += emb[j] * Wt1[tid * 96 + j];
        acc += bt1[tid];
        h1[tid] = (acc >= 0.0f) ? acc : 0.1f * acc;
    }
    __syncthreads();
    if (tid < 256) {
        float acc = 0.0f;
        #pragma unroll 8
        for (int j = 0; j < 96; ++j) acc += h1[j] * Wt2[tid * 96 + j];
        acc += bt2[tid];
        g_tf[tid] = acc;
    }
}

// ---------------------------------------------------------------------------
// Packed f32x2 helpers (two independent IEEE-RN fp32 lanes -> bit-exact)
// ---------------------------------------------------------------------------
__device__ __forceinline__ unsigned long long pack2(float x) {
    unsigned long long r;
    asm("mov.b64 %0, {%1, %1};" : "=l"(r) : "f"(x));
    return r;
}

__device__ __forceinline__ void ffma2(unsigned long long& acc,
                                      unsigned long long a, unsigned long long b) {
    asm("fma.rn.f32x2 %0, %1, %2, %0;" : "+l"(acc) : "l"(a), "l"(b));
}

__device__ __forceinline__ void unpack2(unsigned long long v, float& lo, float& hi) {
    asm("mov.b64 {%0, %1}, %2;" : "=f"(lo), "=f"(hi) : "l"(v));
}

// d_lane = fma(dz,dz, fma(dy,dy, dx*dx)) with dx = nx + (-cx)  (XLA scheme)
__device__ __forceinline__ void dist2x2(unsigned long long nx, unsigned long long ny,
                                        unsigned long long nz,
                                        unsigned long long cx, unsigned long long cy,
                                        unsigned long long cz,
                                        float& d0, float& d1) {
    asm("{\n\t"
        ".reg .b64 dx, dy, dz, t;\n\t"
        "add.rn.f32x2 dx, %2, %5;\n\t"
        "add.rn.f32x2 dy, %3, %6;\n\t"
        "add.rn.f32x2 dz, %4, %7;\n\t"
        "mul.rn.f32x2 t, dx, dx;\n\t"
        "fma.rn.f32x2 t, dy, dy, t;\n\t"
        "fma.rn.f32x2 t, dz, dz, t;\n\t"
        "mov.b64 {%0, %1}, t;\n\t"
        "}"
        : "=f"(d0), "=f"(d1)
        : "l"(nx), "l"(ny), "l"(nz), "l"(cx), "l"(cy), "l"(cz));
}

// Sorted insert, strict '<' (ties keep earlier=lower-index entry) — matches
// the reference top_k semantics when candidates arrive in ascending index.
__device__ __forceinline__ void insert8(float d, int idx, float* bd, int* bi) {
    if (d < bd[KK - 1]) {
        bd[KK - 1] = d;
        bi[KK - 1] = idx;
        #pragma unroll
        for (int q = KK - 1; q > 0; --q) {
            if (bd[q] < bd[q - 1]) {
                float td = bd[q]; bd[q] = bd[q - 1]; bd[q - 1] = td;
                int   ti = bi[q]; bi[q] = bi[q - 1]; bi[q - 1] = ti;
            }
        }
    }
}

union F4U {
    float4 v;
    unsigned long long u[2];
};

// ---------------------------------------------------------------------------
// Kernel 2: warp-cooperative KNN + weights + feature gather, fused.
// One warp processes 2 nodes over ALL 32768 candidates (no partials/merge).
// All 32 lanes share one node's selection state (replicated registers), so
// insert events are warp-correlated: __ballot guard skips ~85% of windows
// uniformly. Candidates processed in ascending index (ffs from LSB), exact
// XLA fmla distances -> selection + ties bit-identical to reference.
// (Proven 494.3us configuration.)
// ---------------------------------------------------------------------------
__global__ void __launch_bounds__(256) k_knn(const int* __restrict__ node_c,
                                             const float* __restrict__ cond_feats) {
    __shared__ __align__(16) float sx[TILE];
    __shared__ __align__(16) float sy[TILE];
    __shared__ __align__(16) float sz[TILE];

    const int tid  = threadIdx.x;
    const int warp = tid >> 5;
    const int lane = tid & 31;
    const int nbase = blockIdx.x * 16 + warp * 2;   // 8 warps x 2 nodes
    const unsigned FULL = 0xffffffffu;

    unsigned long long nx[2], ny[2], nz[2];
    #pragma unroll
    for (int u = 0; u < 2; ++u) {
        int4 nc = ((const int4*)node_c)[nbase + u];
        nx[u] = pack2(__fmul_rn(__fadd_rn((float)nc.y, 8.0f), 0.05f));
        ny[u] = pack2(__fmul_rn(__fadd_rn((float)nc.z, 8.0f), 0.05f));
        nz[u] = pack2(__fmul_rn(__fadd_rn((float)nc.w, 8.0f), 0.05f));
    }

    float bd0[KK], bd1[KK];
    int   bi0[KK], bi1[KK];
    #pragma unroll
    for (int s = 0; s < KK; ++s) {
        bd0[s] = FLT_MAX; bi0[s] = 0x7fffffff;
        bd1[s] = FLT_MAX; bi1[s] = 0x7fffffff;
    }
    float thr0 = FLT_MAX, thr1 = FLT_MAX;

    for (int tile = 0; tile < NTILES; ++tile) {
        __syncthreads();
        {
            const float4* gx = (const float4*)g_cx + tile * (TILE / 4);
            const float4* gy = (const float4*)g_cy + tile * (TILE / 4);
            const float4* gz = (const float4*)g_cz + tile * (TILE / 4);
            #pragma unroll
            for (int i = 0; i < TILE / 4 / 256 * 256; i += 256) {
                ((float4*)sx)[i + tid] = gx[i + tid];
                ((float4*)sy)[i + tid] = gy[i + tid];
                ((float4*)sz)[i + tid] = gz[i + tid];
            }
        }
        __syncthreads();

        #pragma unroll 1
        for (int step = 0; step < TILE / 128; ++step) {
            const int jb = step * 128 + lane * 4;
            F4U X, Y, Z;
            X.v = *(const float4*)&sx[jb];
            Y.v = *(const float4*)&sy[jb];
            Z.v = *(const float4*)&sz[jb];
            const int gbase = tile * TILE + step * 128;

            // ---- node 0 ----
            {
                float d0, d1, d2, d3;
                dist2x2(nx[0], ny[0], nz[0], X.u[0], Y.u[0], Z.u[0], d0, d1);
                dist2x2(nx[0], ny[0], nz[0], X.u[1], Y.u[1], Z.u[1], d2, d3);
                float mn = fminf(fminf(d0, d1), fminf(d2, d3));
                unsigned mask = __ballot_sync(FULL, mn < thr0);
                while (mask) {
                    int b = __ffs(mask) - 1; mask &= mask - 1;
                    float e0 = __shfl_sync(FULL, d0, b);
                    float e1 = __shfl_sync(FULL, d1, b);
                    float e2 = __shfl_sync(FULL, d2, b);
                    float e3 = __shfl_sync(FULL, d3, b);
                    int gi = gbase + b * 4;
                    insert8(e0, gi,     bd0, bi0);
                    insert8(e1, gi + 1, bd0, bi0);
                    insert8(e2, gi + 2, bd0, bi0);
                    insert8(e3, gi + 3, bd0, bi0);
                    thr0 = bd0[KK - 1];
                }
            }
            // ---- node 1 ----
            {
                float d0, d1, d2, d3;
                dist2x2(nx[1], ny[1], nz[1], X.u[0], Y.u[0], Z.u[0], d0, d1);
                dist2x2(nx[1], ny[1], nz[1], X.u[1], Y.u[1], Z.u[1], d2, d3);
                float mn = fminf(fminf(d0, d1), fminf(d2, d3));
                unsigned mask = __ballot_sync(FULL, mn < thr1);
                while (mask) {
                    int b = __ffs(mask) - 1; mask &= mask - 1;
                    float e0 = __shfl_sync(FULL, d0, b);
                    float e1 = __shfl_sync(FULL, d1, b);
                    float e2 = __shfl_sync(FULL, d2, b);
                    float e3 = __shfl_sync(FULL, d3, b);
                    int gi = gbase + b * 4;
                    insert8(e0, gi,     bd1, bi1);
                    insert8(e1, gi + 1, bd1, bi1);
                    insert8(e2, gi + 2, bd1, bi1);
                    insert8(e3, gi + 3, bd1, bi1);
                    thr1 = bd1[KK - 1];
                }
            }
        }
    }

    #pragma unroll
    for (int u = 0; u < 2; ++u) {
        const float* bd = (u == 0) ? bd0 : bd1;
        const int*   bi = (u == 0) ? bi0 : bi1;

        float w[KK];
        float wsum = 0.0f;
        #pragma unroll
        for (int k = 0; k < KK; ++k) {
            float dist = fmaxf(sqrtf(bd[k]), 1e-6f);
            w[k] = 1.0f / dist;
            wsum += w[k];
        }
        #pragma unroll
        for (int k = 0; k < KK; ++k) w[k] = w[k] / wsum;

        const float* rp[KK];
        #pragma unroll
        for (int k = 0; k < KK; ++k) rp[k] = cond_feats + (size_t)bi[k] * CC;

        float* outp = g_favg + (size_t)(nbase + u) * CC;
        #pragma unroll
        for (int j = 0; j < 8; ++j) {
            int c = lane + j * 32;
            float acc = 0.0f;
            #pragma unroll
            for (int k = 0; k < KK; ++k) acc = fmaf(w[k], rp[k][c], acc);
            outp[c] = acc;
        }
    }
}

// ---------------------------------------------------------------------------
// Kernel 4: packed-f32x2 SGEMM  Y[16384,256] = X @ W^T (+bias, act, tf)
// 128x128 tile, 256 threads, 8x8 micro-tile as 4 row-pairs x 8 cols in b64
// (FFMA2). Bit-identical to the scalar version. (Proven 60.5us variant.)
// ---------------------------------------------------------------------------
#define SP 132   // smem pitch (floats)
template<int ACT, int ADDTF>
__global__ void __launch_bounds__(256, 2) k_gemm(const float* __restrict__ X,
                                                 const float* __restrict__ W,
                                                 const float* __restrict__ bias,
                                                 float* __restrict__ Y) {
    __shared__ float As[2][8][SP];
    __shared__ float Bs[2][8][SP];

    const int t   = threadIdx.x;
    const int tx  = t & 15;
    const int ty  = t >> 4;
    const int row0 = blockIdx.x * 128;
    const int col0 = blockIdx.y * 128;

    const int lrow = t >> 1;
    const int lk4  = (t & 1) * 4;
    const float* Ag = X + (size_t)(row0 + lrow) * CC + lk4;
    const float* Bg = W + (size_t)(col0 + lrow) * CC + lk4;

    float4 afrag = *(const float4*)Ag;
    float4 bfrag = *(const float4*)Bg;

    As[0][lk4 + 0][lrow] = afrag.x;
    As[0][lk4 + 1][lrow] = afrag.y;
    As[0][lk4 + 2][lrow] = afrag.z;
    As[0][lk4 + 3][lrow] = afrag.w;
    Bs[0][lk4 + 0][lrow] = bfrag.x;
    Bs[0][lk4 + 1][lrow] = bfrag.y;
    Bs[0][lk4 + 2][lrow] = bfrag.z;
    Bs[0][lk4 + 3][lrow] = bfrag.w;
    __syncthreads();

    unsigned long long acc2[4][8];
    #pragma unroll
    for (int i = 0; i < 4; ++i)
        #pragma unroll
        for (int j = 0; j < 8; ++j) acc2[i][j] = 0ull;

    #pragma unroll 1
    for (int kt = 0; kt < 32; ++kt) {
        int buf = kt & 1;
        if (kt < 31) {
            afrag = *(const float4*)(Ag + (kt + 1) * 8);
            bfrag = *(const float4*)(Bg + (kt + 1) * 8);
        }

        #pragma unroll
        for (int kk = 0; kk < 8; ++kk) {
            F4U a0, a1, b0, b1;
            a0.v = *(const float4*)&As[buf][kk][ty * 8];
            a1.v = *(const float4*)&As[buf][kk][ty * 8 + 4];
            b0.v = *(const float4*)&Bs[buf][kk][tx * 8];
            b1.v = *(const float4*)&Bs[buf][kk][tx * 8 + 4];

            unsigned long long ap[4] = {a0.u[0], a0.u[1], a1.u[0], a1.u[1]};
            unsigned long long bp[8];
            bp[0] = pack2(b0.v.x); bp[1] = pack2(b0.v.y);
            bp[2] = pack2(b0.v.z); bp[3] = pack2(b0.v.w);
            bp[4] = pack2(b1.v.x); bp[5] = pack2(b1.v.y);
            bp[6] = pack2(b1.v.z); bp[7] = pack2(b1.v.w);

            #pragma unroll
            for (int i = 0; i < 4; ++i)
                #pragma unroll
                for (int j = 0; j < 8; ++j)
                    ffma2(acc2[i][j], ap[i], bp[j]);
        }

        if (kt < 31) {
            int nb = buf ^ 1;
            As[nb][lk4 + 0][lrow] = afrag.x;
            As[nb][lk4 + 1][lrow] = afrag.y;
            As[nb][lk4 + 2][lrow] = afrag.z;
            As[nb][lk4 + 3][lrow] = afrag.w;
            Bs[nb][lk4 + 0][lrow] = bfrag.x;
            Bs[nb][lk4 + 1][lrow] = bfrag.y;
            Bs[nb][lk4 + 2][lrow] = bfrag.z;
            Bs[nb][lk4 + 3][lrow] = bfrag.w;
            __syncthreads();
        }
    }

    float bb[8], tf[8];
    #pragma unroll
    for (int j = 0; j < 8; ++j) {
        int c = col0 + tx * 8 + j;
        bb[j] = bias[c];
        if (ADDTF) tf[j] = g_tf[c];
    }

    #pragma unroll
    for (int i2 = 0; i2 < 4; ++i2) {
        float oL[8], oH[8];
        #pragma unroll
        for (int j = 0; j < 8; ++j) {
            float lo, hi;
            unpack2(acc2[i2][j], lo, hi);
            float vL = lo + bb[j];
            float vH = hi + bb[j];
            if (ACT) {
                vL = (vL >= 0.0f) ? vL : 0.1f * vL;
                vH = (vH >= 0.0f) ? vH : 0.1f * vH;
            }
            if (ADDTF) { vL += tf[j]; vH += tf[j]; }
            oL[j] = vL; oH[j] = vH;
        }
        int rL = row0 + ty * 8 + 2 * i2;
        float4* ypL = (float4*)(Y + (size_t)rL * CC + col0 + tx * 8);
        ypL[0] = make_float4(oL[0], oL[1], oL[2], oL[3]);
        ypL[1] = make_float4(oL[4], oL[5], oL[6], oL[7]);
        float4* ypH = (float4*)(Y + (size_t)(rL + 1) * CC + col0 + tx * 8);
        ypH[0] = make_float4(oH[0], oH[1], oH[2], oH[3]);
        ypH[1] = make_float4(oH[4], oH[5], oH[6], oH[7]);
    }
}

// ---------------------------------------------------------------------------
extern "C" void kernel_launch(void* const* d_in, const int* in_sizes, int n_in,
                              void* d_out, int out_size) {
    const int*   node_c     = (const int*)d_in[0];
    const int*   cond_c     = (const int*)d_in[1];
    const float* cond_feats = (const float*)d_in[2];
    const float* t          = (const float*)d_in[3];
    const float* W_proj     = (const float*)d_in[4];
    const float* b_proj     = (const float*)d_in[5];
    const float* W_l1       = (const float*)d_in[6];
    const float* b_l1       = (const float*)d_in[7];
    const float* W_l2       = (const float*)d_in[8];
    const float* b_l2       = (const float*)d_in[9];
    const float* W_t1       = (const float*)d_in[10];
    const float* b_t1       = (const float*)d_in[11];
    const float* W_t2       = (const float*)d_in[12];
    const float* b_t2       = (const float*)d_in[13];
    float* out = (float*)d_out;

    float* h1; cudaGetSymbolAddress((void**)&h1, g_h1);
    float* h2; cudaGetSymbolAddress((void**)&h2, g_h2);
    float* fa; cudaGetSymbolAddress((void**)&fa, g_favg);

    k_prep<<<MM / 256, 256>>>(cond_c);
    k_tfeats<<<1, 256>>>(t, W_t1, b_t1, W_t2, b_t2);

    k_knn<<<NN / 16, 256>>>(node_c, cond_feats);   // 1024 blocks, 8 warps x 2 nodes

    dim3 gg(NN / 128, CC / 128);   // 128 x 2 = 256 blocks
    k_gemm<0, 0><<<gg, 256>>>(fa, W_proj, b_proj, h1);
    k_gemm<1, 0><<<gg, 256>>>(h1, W_l1, b_l1, h2);
    k_gemm<0, 1><<<gg, 256>>>(h2, W_l2, b_l2, out);

    (void)in_sizes; (void)n_in; (void)out_size;
}